// round 9
// baseline (speedup 1.0000x reference)
#include <cuda_runtime.h>
#include <cuda_bf16.h>
#include <math.h>
#include <stdint.h>

#define BATCH 8
#define CC 64
#define NN 110592               // 48*48*48
#define SPLITS 72
#define CHUNK 1536              // 72*1536 = 110592
#define TILE 128                // n per pipeline step
#define NSTEP (CHUNK / TILE)    // 12
#define OTILES 4                // tiles per CTA in out_kernel
#define SROW 144                // 64-col bf16 row stride bytes (128B + 16B pad)
#define SROW2 272               // 128-col bf16 row stride bytes (256B + 16B pad)

// Scratch (device globals; no allocation allowed)
__device__ float g_Gpart[SPLITS * BATCH * CC * CC];          // ~9.4 MB
__device__ __nv_bfloat16 g_aff_bf16[BATCH * CC * CC];        // 64 KB

// ---------------------------------------------------------------------------
// PTX helpers
// ---------------------------------------------------------------------------
__device__ __forceinline__ uint32_t s2u(const void* p) {
    uint32_t a;
    asm("{ .reg .u64 t; cvta.to.shared.u64 t, %1; cvt.u32.u64 %0, t; }"
        : "=r"(a) : "l"(p));
    return a;
}

__device__ __forceinline__ void ldsm4(uint32_t* r, uint32_t addr) {
    asm volatile("ldmatrix.sync.aligned.m8n8.x4.shared.b16 {%0,%1,%2,%3}, [%4];"
                 : "=r"(r[0]), "=r"(r[1]), "=r"(r[2]), "=r"(r[3]) : "r"(addr));
}

__device__ __forceinline__ void ldsm4t(uint32_t* r, uint32_t addr) {
    asm volatile("ldmatrix.sync.aligned.m8n8.x4.trans.shared.b16 {%0,%1,%2,%3}, [%4];"
                 : "=r"(r[0]), "=r"(r[1]), "=r"(r[2]), "=r"(r[3]) : "r"(addr));
}

__device__ __forceinline__ void mma_bf16(float* d, const uint32_t* a, const uint32_t* b) {
    asm volatile(
        "mma.sync.aligned.m16n8k16.row.col.f32.bf16.bf16.f32 "
        "{%0,%1,%2,%3}, {%4,%5,%6,%7}, {%8,%9}, {%0,%1,%2,%3};"
        : "+f"(d[0]), "+f"(d[1]), "+f"(d[2]), "+f"(d[3])
        : "r"(a[0]), "r"(a[1]), "r"(a[2]), "r"(a[3]), "r"(b[0]), "r"(b[1]));
}

__device__ __forceinline__ uint2 f4_to_bf(float4 v) {
    __nv_bfloat162 p0 = __float22bfloat162_rn(make_float2(v.x, v.y));
    __nv_bfloat162 p1 = __float22bfloat162_rn(make_float2(v.z, v.w));
    uint2 u;
    u.x = *(uint32_t*)&p0;
    u.y = *(uint32_t*)&p1;
    return u;
}

// ---------------------------------------------------------------------------
// Kernel A: partial Gram. G_s[c][d] = sum_{n in chunk s} K[c,n]K[d,n]
// grid = (72, 8) = 576 CTAs (~4/SM), 256 threads (8 warps).
// Warp tiling 4(m) x 2(n): warp covers 16 c-rows x 32 d-cols (LDS -33% vs 1x8).
// 128-wide n tiles, register-prefetch double buffering, bf16 MMA / fp32 acc.
// ---------------------------------------------------------------------------
__global__ __launch_bounds__(256) void gram_kernel(const float* __restrict__ x) {
    const int s = blockIdx.x, b = blockIdx.y;
    const float* __restrict__ xb = x + (size_t)b * CC * NN + (size_t)s * CHUNK;

    __shared__ __align__(16) unsigned char kb[2][64 * SROW2];

    const int tid = threadIdx.x;
    const int lane = tid & 31, w = tid >> 5;
    const int wm = w >> 1, wn = w & 1;          // 4 x 2 warp grid
    const int grp = lane >> 3, wi = lane & 7;

    const uint32_t k0 = s2u(kb[0]);
    const uint32_t bufstep = 64 * SROW2;
    // A frag (16m x 16k): rows 16*wm + wi + (grp&1)*8, byte col (grp>>1)*16
    const uint32_t aAddr = k0 + (uint32_t)((16 * wm + wi + (grp & 1) * 8) * SROW2 + (grp >> 1) * 16);
    // B frag (8n x 32k): rows 32*wn + 8*j + wi, byte col grp*16
    const uint32_t bAddr = k0 + (uint32_t)((32 * wn + wi) * SROW2 + grp * 16);

    float acc[4][4];                            // 4 n-blocks of 8, m=16
#pragma unroll
    for (int j = 0; j < 4; j++)
#pragma unroll
        for (int q = 0; q < 4; q++) acc[j][q] = 0.0f;

    // thread loads rows c = w + 8i, cols lane*4..lane*4+3 (512B/warp contiguous)
    float4 v[8];
#pragma unroll
    for (int i = 0; i < 8; i++)
        v[i] = *(const float4*)(xb + (size_t)(w + 8 * i) * NN + lane * 4);
#pragma unroll
    for (int i = 0; i < 8; i++)
        *(uint2*)(kb[0] + (w + 8 * i) * SROW2 + lane * 8) = f4_to_bf(v[i]);
    __syncthreads();

    for (int t = 0; t < NSTEP; t++) {
        const uint32_t cur = (t & 1) * bufstep;
        if (t + 1 < NSTEP) {
            const float* src = xb + (size_t)(t + 1) * TILE;
#pragma unroll
            for (int i = 0; i < 8; i++)
                v[i] = *(const float4*)(src + (size_t)(w + 8 * i) * NN + lane * 4);
        }
#pragma unroll
        for (int kd = 0; kd < 4; kd++) {
            uint32_t a0[4], a1[4];
            ldsm4(a0, aAddr + cur + kd * 64);
            ldsm4(a1, aAddr + cur + kd * 64 + 32);
#pragma unroll
            for (int j = 0; j < 4; j++) {
                uint32_t bfr[4];
                ldsm4(bfr, bAddr + cur + j * 8 * SROW2 + kd * 64);
                mma_bf16(acc[j], a0, bfr);
                mma_bf16(acc[j], a1, bfr + 2);
            }
        }
        if (t + 1 < NSTEP) {
            unsigned char* dst = kb[(t + 1) & 1];
#pragma unroll
            for (int i = 0; i < 8; i++)
                *(uint2*)(dst + (w + 8 * i) * SROW2 + lane * 8) = f4_to_bf(v[i]);
            __syncthreads();
        }
    }

    float* gp = g_Gpart + (size_t)(s * BATCH + b) * CC * CC;
    const int r0 = lane >> 2, cq = 2 * (lane & 3);
#pragma unroll
    for (int j = 0; j < 4; j++) {
        int col = 32 * wn + 8 * j + cq;
        int row = 16 * wm + r0;
        *(float2*)&gp[row * CC + col]       = make_float2(acc[j][0], acc[j][1]);
        *(float2*)&gp[(row + 8) * CC + col] = make_float2(acc[j][2], acc[j][3]);
    }
}

// ---------------------------------------------------------------------------
// Kernel B: reduce partials -> G, m3 = G*G, affinity = sigmoid(m3) -> bf16
// ---------------------------------------------------------------------------
__global__ __launch_bounds__(256) void affinity_kernel() {
    const int b = blockIdx.x;
    __shared__ float G[CC * CC];

    for (int e = threadIdx.x; e < CC * CC; e += 256) {
        float sum = 0.0f;
        for (int s = 0; s < SPLITS; s++)
            sum += g_Gpart[(size_t)(s * BATCH + b) * CC * CC + e];
        G[e] = sum;
    }
    __syncthreads();

    for (int idx = threadIdx.x; idx < CC * CC; idx += 256) {
        int c = idx >> 6;
        int e = idx & 63;
        float m = 0.0f;
#pragma unroll 16
        for (int d = 0; d < CC; d++) m += G[c * CC + d] * G[d * CC + e];
        float sig = 1.0f / (1.0f + expf(-m));
        g_aff_bf16[b * CC * CC + idx] = __float2bfloat16(sig);
    }
}

// ---------------------------------------------------------------------------
// Kernel C: out[c,n] = gamma * sum_d aff[c,d]*K[d,n] + x[c,n]
// grid = (NN/128/OTILES = 216, BATCH), 256 threads (8 warps).
// Each CTA processes OTILES=4 consecutive 128-wide tiles with register-prefetch
// double buffering; affinity smem load amortized. Warp w: n-cols 16w..16w+15,
// all 64 c-rows. Residual x reread from gmem (L2-hot).
// ---------------------------------------------------------------------------
__global__ __launch_bounds__(256) void out_kernel(const float* __restrict__ x,
                                                  const float* __restrict__ gamma_p,
                                                  float* __restrict__ out) {
    const int nb = blockIdx.x, b = blockIdx.y;
    const float* __restrict__ xb = x + (size_t)b * CC * NN + (size_t)nb * (OTILES * TILE);
    float* __restrict__ ob = out + (size_t)b * CC * NN + (size_t)nb * (OTILES * TILE);

    __shared__ __align__(16) unsigned char kb[2][64 * SROW2];  // x tiles bf16 [d][n]
    __shared__ __align__(16) unsigned char ab[64 * SROW];      // affinity bf16 [c][d]

    const int tid = threadIdx.x;
    const int lane = tid & 31, w = tid >> 5;
    const float g = *gamma_p;

    const __nv_bfloat16* affb = g_aff_bf16 + (size_t)b * CC * CC;
#pragma unroll
    for (int i = 0; i < 2; i++) {
        int f = tid + 256 * i;
        int r = f >> 3, sg = f & 7;
        *(uint4*)(ab + r * SROW + sg * 16) = *(const uint4*)(affb + r * CC + sg * 8);
    }

    float4 v[8];
#pragma unroll
    for (int i = 0; i < 8; i++)
        v[i] = *(const float4*)(xb + (size_t)(w + 8 * i) * NN + lane * 4);
#pragma unroll
    for (int i = 0; i < 8; i++)
        *(uint2*)(kb[0] + (w + 8 * i) * SROW2 + lane * 8) = f4_to_bf(v[i]);
    __syncthreads();

    const int grp = lane >> 3, wi = lane & 7;
    const uint32_t ab0 = s2u(ab), kb0 = s2u(kb[0]);
    const uint32_t bufstep = 64 * SROW2;
    // A = aff [c][d] row-major
    const uint32_t aAddr = ab0 + (uint32_t)((wi + (grp & 1) * 8) * SROW + (grp >> 1) * 16);
    // B via trans ldmatrix: 16x16 tiles at rows k(d), cols 16w..16w+15
    const uint32_t bAddr = kb0 + (uint32_t)((wi + (grp & 1) * 8) * SROW2 + 32 * w + (grp >> 1) * 16);

    const int r0 = lane >> 2, cq = 2 * (lane & 3);

    for (int t = 0; t < OTILES; t++) {
        const uint32_t cur = (t & 1) * bufstep;
        if (t + 1 < OTILES) {
            const float* src = xb + (size_t)(t + 1) * TILE;
#pragma unroll
            for (int i = 0; i < 8; i++)
                v[i] = *(const float4*)(src + (size_t)(w + 8 * i) * NN + lane * 4);
        }

        float acc[4][2][4];
#pragma unroll
        for (int mi = 0; mi < 4; mi++)
#pragma unroll
            for (int nj = 0; nj < 2; nj++)
#pragma unroll
                for (int q = 0; q < 4; q++) acc[mi][nj][q] = 0.0f;

#pragma unroll
        for (int ks = 0; ks < 4; ks++) {
            uint32_t bfr[4];
            ldsm4t(bfr, bAddr + cur + ks * 16 * SROW2);
#pragma unroll
            for (int mi = 0; mi < 4; mi++) {
                uint32_t afr[4];
                ldsm4(afr, aAddr + mi * 16 * SROW + 32 * ks);
                mma_bf16(acc[mi][0], afr, bfr);
                mma_bf16(acc[mi][1], afr, bfr + 2);
            }
        }

        const float* xt = xb + (size_t)t * TILE;
        float* ot = ob + (size_t)t * TILE;
#pragma unroll
        for (int mi = 0; mi < 4; mi++)
#pragma unroll
            for (int nj = 0; nj < 2; nj++) {
                int nl = 16 * w + 8 * nj + cq;
                int c = 16 * mi + r0;
                size_t i0 = (size_t)c * NN + nl;
                size_t i1 = (size_t)(c + 8) * NN + nl;
                float2 x0 = *(const float2*)(xt + i0);   // L2 hit
                float2 x1 = *(const float2*)(xt + i1);
                *(float2*)(ot + i0) = make_float2(g * acc[mi][nj][0] + x0.x,
                                                  g * acc[mi][nj][1] + x0.y);
                *(float2*)(ot + i1) = make_float2(g * acc[mi][nj][2] + x1.x,
                                                  g * acc[mi][nj][3] + x1.y);
            }

        if (t + 1 < OTILES) {
            unsigned char* dst = kb[(t + 1) & 1];
#pragma unroll
            for (int i = 0; i < 8; i++)
                *(uint2*)(dst + (w + 8 * i) * SROW2 + lane * 8) = f4_to_bf(v[i]);
            __syncthreads();
        }
    }
}

extern "C" void kernel_launch(void* const* d_in, const int* in_sizes, int n_in,
                              void* d_out, int out_size) {
    const float* x       = (const float*)d_in[0];
    const float* gamma_p = (const float*)d_in[1];
    float* out           = (float*)d_out;

    dim3 gridA(SPLITS, BATCH);
    gram_kernel<<<gridA, 256>>>(x);

    affinity_kernel<<<BATCH, 256>>>();

    dim3 gridC(NN / TILE / OTILES, BATCH);
    out_kernel<<<gridC, 256>>>(x, gamma_p, out);
}

// round 15
// speedup vs baseline: 1.2392x; 1.2392x over previous
#include <cuda_runtime.h>
#include <cuda_bf16.h>
#include <math.h>
#include <stdint.h>

#define BATCH 8
#define CC 64
#define NN 110592               // 48*48*48
#define SPLITS 36
#define CHUNK 3072              // 36*3072 = 110592
#define TILE 128                // n per pipeline step
#define NSTEP (CHUNK / TILE)    // 24
#define SROW 144                // 64-col bf16 smem row stride bytes (128B + 16B pad)
#define SROW2 272               // 128-col bf16 smem row stride bytes (256B + 16B pad)

// Scratch (device globals; no allocation allowed)
__device__ float g_Gpart[SPLITS * BATCH * CC * CC];          // ~4.7 MB
__device__ __nv_bfloat16 g_aff_bf16[BATCH * CC * CC];        // 64 KB

// ---------------------------------------------------------------------------
// PTX helpers
// ---------------------------------------------------------------------------
__device__ __forceinline__ uint32_t s2u(const void* p) {
    uint32_t a;
    asm("{ .reg .u64 t; cvta.to.shared.u64 t, %1; cvt.u32.u64 %0, t; }"
        : "=r"(a) : "l"(p));
    return a;
}

__device__ __forceinline__ void ldsm4(uint32_t* r, uint32_t addr) {
    asm volatile("ldmatrix.sync.aligned.m8n8.x4.shared.b16 {%0,%1,%2,%3}, [%4];"
                 : "=r"(r[0]), "=r"(r[1]), "=r"(r[2]), "=r"(r[3]) : "r"(addr));
}

__device__ __forceinline__ void ldsm4t(uint32_t* r, uint32_t addr) {
    asm volatile("ldmatrix.sync.aligned.m8n8.x4.trans.shared.b16 {%0,%1,%2,%3}, [%4];"
                 : "=r"(r[0]), "=r"(r[1]), "=r"(r[2]), "=r"(r[3]) : "r"(addr));
}

__device__ __forceinline__ void mma_bf16(float* d, const uint32_t* a, const uint32_t* b) {
    asm volatile(
        "mma.sync.aligned.m16n8k16.row.col.f32.bf16.bf16.f32 "
        "{%0,%1,%2,%3}, {%4,%5,%6,%7}, {%8,%9}, {%0,%1,%2,%3};"
        : "+f"(d[0]), "+f"(d[1]), "+f"(d[2]), "+f"(d[3])
        : "r"(a[0]), "r"(a[1]), "r"(a[2]), "r"(a[3]), "r"(b[0]), "r"(b[1]));
}

__device__ __forceinline__ uint2 f4_to_bf(float4 v) {
    __nv_bfloat162 p0 = __float22bfloat162_rn(make_float2(v.x, v.y));
    __nv_bfloat162 p1 = __float22bfloat162_rn(make_float2(v.z, v.w));
    uint2 u;
    u.x = *(uint32_t*)&p0;
    u.y = *(uint32_t*)&p1;
    return u;
}

// ---------------------------------------------------------------------------
// Kernel A: partial Gram. G_s[c][d] = sum_{n in chunk s} K[c,n]K[d,n]
// grid = (36, 8) = 288 CTAs (~2/SM), 256 threads (8 warps).  [R8 proven]
// 128-wide n tiles, register-prefetch double buffering, bf16 MMA / fp32 acc.
// Warp w computes d-cols 8w..8w+7 for all 64 c-rows.
// ---------------------------------------------------------------------------
__global__ __launch_bounds__(256) void gram_kernel(const float* __restrict__ x) {
    const int s = blockIdx.x, b = blockIdx.y;
    const float* __restrict__ xb = x + (size_t)b * CC * NN + (size_t)s * CHUNK;

    __shared__ __align__(16) unsigned char kb[2][64 * SROW2];

    const int tid = threadIdx.x;
    const int lane = tid & 31, w = tid >> 5;
    const int grp = lane >> 3, wi = lane & 7;

    const uint32_t k0 = s2u(kb[0]);
    const uint32_t bufstep = 64 * SROW2;
    // A frag (16m x 16k per ldsm4): g0 (m0..7,k0) g1 (m8..15,k0) g2 (m0..7,+16B) g3 (m8..15,+16B)
    const uint32_t aAddr = k0 + (uint32_t)((wi + (grp & 1) * 8) * SROW2 + (grp >> 1) * 16);
    // B frag (8d x 32k per ldsm4): tile g = rows 8w+wi, byte col g*16
    const uint32_t bAddr = k0 + (uint32_t)((8 * w + wi) * SROW2 + grp * 16);

    float acc[4][4];
#pragma unroll
    for (int mi = 0; mi < 4; mi++)
#pragma unroll
        for (int q = 0; q < 4; q++) acc[mi][q] = 0.0f;

    // thread loads rows c = w + 8i, cols lane*4..lane*4+3 (512B/warp contiguous)
    float4 v[8];
#pragma unroll
    for (int i = 0; i < 8; i++)
        v[i] = *(const float4*)(xb + (size_t)(w + 8 * i) * NN + lane * 4);
#pragma unroll
    for (int i = 0; i < 8; i++)
        *(uint2*)(kb[0] + (w + 8 * i) * SROW2 + lane * 8) = f4_to_bf(v[i]);
    __syncthreads();

    for (int t = 0; t < NSTEP; t++) {
        const uint32_t cur = (t & 1) * bufstep;
        if (t + 1 < NSTEP) {
            const float* src = xb + (size_t)(t + 1) * TILE;
#pragma unroll
            for (int i = 0; i < 8; i++)
                v[i] = *(const float4*)(src + (size_t)(w + 8 * i) * NN + lane * 4);
        }
#pragma unroll
        for (int kd = 0; kd < 4; kd++) {
            uint32_t bfr[4];
            ldsm4(bfr, bAddr + cur + kd * 64);
#pragma unroll
            for (int mi = 0; mi < 4; mi++) {
                uint32_t a0[4], a1[4];
                ldsm4(a0, aAddr + cur + mi * 16 * SROW2 + kd * 64);
                ldsm4(a1, aAddr + cur + mi * 16 * SROW2 + kd * 64 + 32);
                mma_bf16(acc[mi], a0, bfr);
                mma_bf16(acc[mi], a1, bfr + 2);
            }
        }
        if (t + 1 < NSTEP) {
            unsigned char* dst = kb[(t + 1) & 1];
#pragma unroll
            for (int i = 0; i < 8; i++)
                *(uint2*)(dst + (w + 8 * i) * SROW2 + lane * 8) = f4_to_bf(v[i]);
            __syncthreads();
        }
    }

    float* gp = g_Gpart + (size_t)(s * BATCH + b) * CC * CC;
    const int r0 = lane >> 2, cq = 2 * (lane & 3);
#pragma unroll
    for (int mi = 0; mi < 4; mi++) {
        int col = 8 * w + cq;
        __stcs((float2*)&gp[(16 * mi + r0) * CC + col],
               make_float2(acc[mi][0], acc[mi][1]));
        __stcs((float2*)&gp[(16 * mi + r0 + 8) * CC + col],
               make_float2(acc[mi][2], acc[mi][3]));
    }
}

// ---------------------------------------------------------------------------
// Kernel B: reduce partials -> G, m3 = G*G, affinity = sigmoid(m3) -> bf16
// Reduction unrolled x4 (independent accumulators -> MLP 4, streaming loads).
// ---------------------------------------------------------------------------
__global__ __launch_bounds__(256) void affinity_kernel() {
    const int b = blockIdx.x;
    __shared__ float G[CC * CC];

    for (int e = threadIdx.x; e < CC * CC; e += 256) {
        float s0 = 0.0f, s1 = 0.0f, s2 = 0.0f, s3 = 0.0f;
#pragma unroll
        for (int s = 0; s < SPLITS; s += 4) {
            s0 += __ldcs(&g_Gpart[(size_t)((s + 0) * BATCH + b) * CC * CC + e]);
            s1 += __ldcs(&g_Gpart[(size_t)((s + 1) * BATCH + b) * CC * CC + e]);
            s2 += __ldcs(&g_Gpart[(size_t)((s + 2) * BATCH + b) * CC * CC + e]);
            s3 += __ldcs(&g_Gpart[(size_t)((s + 3) * BATCH + b) * CC * CC + e]);
        }
        G[e] = (s0 + s1) + (s2 + s3);
    }
    __syncthreads();

    for (int idx = threadIdx.x; idx < CC * CC; idx += 256) {
        int c = idx >> 6;
        int e = idx & 63;
        float m = 0.0f;
#pragma unroll 16
        for (int d = 0; d < CC; d++) m += G[c * CC + d] * G[d * CC + e];
        float sig = 1.0f / (1.0f + expf(-m));
        g_aff_bf16[b * CC * CC + idx] = __float2bfloat16(sig);
    }
}

// ---------------------------------------------------------------------------
// Kernel C: out[c,n] = gamma * sum_d aff[c,d]*K[d,n] + x[c,n]
// grid = (NN/128, BATCH) = 6912 CTAs, 256 threads (8 warps).  [R8 proven]
// Warp w: n-cols 16w..16w+15, all 64 c-rows. Residual x reread from gmem
// (L2-hot). Output written with streaming stores to protect L2 for x.
// ---------------------------------------------------------------------------
__global__ __launch_bounds__(256) void out_kernel(const float* __restrict__ x,
                                                  const float* __restrict__ gamma_p,
                                                  float* __restrict__ out) {
    const int nb = blockIdx.x, b = blockIdx.y;
    const float* __restrict__ xb = x + (size_t)b * CC * NN + (size_t)nb * TILE;
    float* __restrict__ ob = out + (size_t)b * CC * NN + (size_t)nb * TILE;

    __shared__ __align__(16) unsigned char kb[64 * SROW2];   // x tile bf16 [d][n]
    __shared__ __align__(16) unsigned char ab[64 * SROW];    // affinity bf16 [c][d]

    const int tid = threadIdx.x;
    const int lane = tid & 31, w = tid >> 5;

    const __nv_bfloat16* affb = g_aff_bf16 + (size_t)b * CC * CC;
#pragma unroll
    for (int i = 0; i < 2; i++) {
        int f = tid + 256 * i;
        int r = f >> 3, sg = f & 7;
        *(uint4*)(ab + r * SROW + sg * 16) = *(const uint4*)(affb + r * CC + sg * 8);
    }
#pragma unroll
    for (int i = 0; i < 8; i++) {
        float4 v = *(const float4*)(xb + (size_t)(w + 8 * i) * NN + lane * 4);
        *(uint2*)(kb + (w + 8 * i) * SROW2 + lane * 8) = f4_to_bf(v);
    }
    __syncthreads();

    const int grp = lane >> 3, wi = lane & 7;
    const uint32_t ab0 = s2u(ab), kb0 = s2u(kb);
    // A = aff [c][d] row-major
    const uint32_t aAddr = ab0 + (uint32_t)((wi + (grp & 1) * 8) * SROW + (grp >> 1) * 16);
    // B via trans ldmatrix: 16x16 tiles at rows k(d), cols 16w..16w+15
    const uint32_t bAddr = kb0 + (uint32_t)((wi + (grp & 1) * 8) * SROW2 + 32 * w + (grp >> 1) * 16);

    float acc[4][2][4];
#pragma unroll
    for (int mi = 0; mi < 4; mi++)
#pragma unroll
        for (int nj = 0; nj < 2; nj++)
#pragma unroll
            for (int q = 0; q < 4; q++) acc[mi][nj][q] = 0.0f;

#pragma unroll
    for (int ks = 0; ks < 4; ks++) {
        uint32_t bfr[4];
        ldsm4t(bfr, bAddr + ks * 16 * SROW2);
#pragma unroll
        for (int mi = 0; mi < 4; mi++) {
            uint32_t afr[4];
            ldsm4(afr, aAddr + mi * 16 * SROW + 32 * ks);
            mma_bf16(acc[mi][0], afr, bfr);
            mma_bf16(acc[mi][1], afr, bfr + 2);
        }
    }

    const float g = *gamma_p;
    const int r0 = lane >> 2, cq = 2 * (lane & 3);
#pragma unroll
    for (int mi = 0; mi < 4; mi++)
#pragma unroll
        for (int nj = 0; nj < 2; nj++) {
            int nl = 16 * w + 8 * nj + cq;
            int c = 16 * mi + r0;
            size_t i0 = (size_t)c * NN + nl;
            size_t i1 = (size_t)(c + 8) * NN + nl;
            float2 x0 = *(const float2*)(xb + i0);   // L2 hit
            float2 x1 = *(const float2*)(xb + i1);
            __stcs((float2*)(ob + i0), make_float2(g * acc[mi][nj][0] + x0.x,
                                                   g * acc[mi][nj][1] + x0.y));
            __stcs((float2*)(ob + i1), make_float2(g * acc[mi][nj][2] + x1.x,
                                                   g * acc[mi][nj][3] + x1.y));
        }
}

extern "C" void kernel_launch(void* const* d_in, const int* in_sizes, int n_in,
                              void* d_out, int out_size) {
    const float* x       = (const float*)d_in[0];
    const float* gamma_p = (const float*)d_in[1];
    float* out           = (float*)d_out;

    dim3 gridA(SPLITS, BATCH);
    gram_kernel<<<gridA, 256>>>(x);

    affinity_kernel<<<BATCH, 256>>>();

    dim3 gridC(NN / TILE, BATCH);
    out_kernel<<<gridC, 256>>>(x, gamma_p, out);
}